// round 1
// baseline (speedup 1.0000x reference)
#include <cuda_runtime.h>
#include <cuda_bf16.h>
#include <math.h>

// Problem constants
#define BB   512
#define LL   200
#define EE   256
#define HH   128        // per-direction hidden
#define DD   256
#define TT   6
#define GATES 512       // 4*H
#define MROWS (BB*LL)   // 102400

typedef unsigned long long u64;

// ---------------- scratch (device globals: allocation-free rule) --------------
__device__ float g_xg[(size_t)MROWS * 1024];     // input-gate preactivations, both dirs
__device__ float g_h [(size_t)MROWS * DD];       // concat BiLSTM hidden
__device__ float g_h1[(size_t)MROWS * DD];
__device__ float g_h2[(size_t)MROWS * DD];
__device__ float g_logits[(size_t)MROWS * TT];
__device__ float g_Wstack[1024 * EE];            // [Wih_f; Wih_b]
__device__ float g_bstack[1024];                 // bih+bhh per dir
__device__ float g_WhhT_f[HH * GATES];           // k-major transposed Whh
__device__ float g_WhhT_b[HH * GATES];

// ---------------- f32x2 helpers (B300: FFMA rt=2, FFMA2 doubles MAC rate) ----
__device__ __forceinline__ u64 pack2(float lo, float hi) {
    u64 r; asm("mov.b64 %0, {%1, %2};" : "=l"(r) : "f"(lo), "f"(hi)); return r;
}
__device__ __forceinline__ void unpack2(u64 v, float& lo, float& hi) {
    asm("mov.b64 {%0, %1}, %2;" : "=f"(lo), "=f"(hi) : "l"(v));
}
__device__ __forceinline__ void ffma2(u64& d, u64 a, u64 b) {
    asm("fma.rn.f32x2 %0, %1, %2, %0;" : "+l"(d) : "l"(a), "l"(b));
}

// Accurate-under-fast-math activations (avoid tanh.approx!)
__device__ __forceinline__ float sigm(float x) { return 1.0f / (1.0f + expf(-x)); }
__device__ __forceinline__ float tanh_acc(float x) {
    float e = expf(2.0f * x);
    return 1.0f - 2.0f / (e + 1.0f);
}
__device__ __forceinline__ float leaky(float x) { return (x >= 0.0f) ? x : 0.01f * x; }

// ---------------- prep: stack Wih, combine biases, transpose Whh -------------
__global__ void prep_kernel(const float* __restrict__ Wih_f, const float* __restrict__ Wih_b,
                            const float* __restrict__ bih_f, const float* __restrict__ bhh_f,
                            const float* __restrict__ bih_b, const float* __restrict__ bhh_b,
                            const float* __restrict__ Whh_f, const float* __restrict__ Whh_b) {
    int i = blockIdx.x * 256 + threadIdx.x;       // grid covers 131072
    if (i < GATES * EE) {
        g_Wstack[i] = Wih_f[i];
        g_Wstack[GATES * EE + i] = Wih_b[i];
    }
    if (i < GATES * HH) {
        int j = i >> 7, k = i & 127;              // Whh[j][k] -> WhhT[k][j]
        g_WhhT_f[k * GATES + j] = Whh_f[i];
        g_WhhT_b[k * GATES + j] = Whh_b[i];
    }
    if (i < GATES) {
        g_bstack[i]         = bih_f[i] + bhh_f[i];
        g_bstack[GATES + i] = bih_b[i] + bhh_b[i];
    }
}

// ---------------- 64x64 fp32 GEMM, C = act(A @ Bw^T + bias) ------------------
// Bw is [N,K] row-major (PyTorch Linear layout). GATHER: A row m = emb[tok[m]].
template<int GATHER, int ACT>
__global__ void __launch_bounds__(256) gemm64x64(
    const float* __restrict__ A, const int* __restrict__ tok,
    const float* __restrict__ emb,
    const float* __restrict__ Bw, const float* __restrict__ bias,
    float* __restrict__ C, int N, int K)
{
    __shared__ float As[16][64];
    __shared__ float Bs[16][64];
    const int tid = threadIdx.x;
    const int mbase = blockIdx.y * 64;
    const int nbase = blockIdx.x * 64;
    const int lr = tid >> 2;            // 0..63
    const int lc = (tid & 3) << 2;      // 0,4,8,12
    const float* arow;
    if (GATHER) arow = emb + (size_t)tok[mbase + lr] * K;
    else        arow = A   + (size_t)(mbase + lr) * K;
    const float* brow = Bw + (size_t)(nbase + lr) * K;

    u64 acc[2][4];
#pragma unroll
    for (int i = 0; i < 2; i++)
#pragma unroll
        for (int j = 0; j < 4; j++) acc[i][j] = 0ull;

    const int m0 = (tid >> 4) << 2;
    const int n0 = (tid & 15) << 2;

    for (int kt = 0; kt < K; kt += 16) {
        float4 a4 = *(const float4*)(arow + kt + lc);
        float4 b4 = *(const float4*)(brow + kt + lc);
        As[lc + 0][lr] = a4.x; As[lc + 1][lr] = a4.y;
        As[lc + 2][lr] = a4.z; As[lc + 3][lr] = a4.w;
        Bs[lc + 0][lr] = b4.x; Bs[lc + 1][lr] = b4.y;
        Bs[lc + 2][lr] = b4.z; Bs[lc + 3][lr] = b4.w;
        __syncthreads();
#pragma unroll
        for (int kk = 0; kk < 16; kk++) {
            ulonglong2 av = *(const ulonglong2*)(&As[kk][m0]);  // m-pairs packed free
            float4 bv = *(const float4*)(&Bs[kk][n0]);
            u64 bb0 = pack2(bv.x, bv.x);
            u64 bb1 = pack2(bv.y, bv.y);
            u64 bb2 = pack2(bv.z, bv.z);
            u64 bb3 = pack2(bv.w, bv.w);
            ffma2(acc[0][0], av.x, bb0); ffma2(acc[0][1], av.x, bb1);
            ffma2(acc[0][2], av.x, bb2); ffma2(acc[0][3], av.x, bb3);
            ffma2(acc[1][0], av.y, bb0); ffma2(acc[1][1], av.y, bb1);
            ffma2(acc[1][2], av.y, bb2); ffma2(acc[1][3], av.y, bb3);
        }
        __syncthreads();
    }

    float o[4][4];
#pragma unroll
    for (int mp = 0; mp < 2; mp++)
#pragma unroll
        for (int n = 0; n < 4; n++) unpack2(acc[mp][n], o[2 * mp][n], o[2 * mp + 1][n]);

    float bsv[4];
#pragma unroll
    for (int n = 0; n < 4; n++) bsv[n] = bias[nbase + n0 + n];
#pragma unroll
    for (int i = 0; i < 4; i++) {
        float4 v;
        float* vv = (float*)&v;
#pragma unroll
        for (int n = 0; n < 4; n++) {
            float x = o[i][n] + bsv[n];
            if (ACT) x = leaky(x);
            vv[n] = x;
        }
        *(float4*)(&C[(size_t)(mbase + m0 + i) * N + nbase + n0]) = v;
    }
}

// ---------------- persistent BiLSTM: 1 block = (dir, 8 batch rows) -----------
__global__ void __launch_bounds__(256) lstm_kernel(
    const float* __restrict__ xg,
    const float* __restrict__ WhhT_f, const float* __restrict__ WhhT_b,
    float* __restrict__ hout)
{
    __shared__ float sh_h[HH][8];       // transposed: batch rows adjacent -> free f32x2 pairs
    __shared__ float sh_c[8][HH];
    __shared__ float sh_g[8][GATES];
    const int tid = threadIdx.x;
    const int dir = blockIdx.x & 1;
    const int grp = blockIdx.x >> 1;
    const int b0 = grp * 8;
    const float* __restrict__ W = dir ? WhhT_b : WhhT_f;

    for (int i = tid; i < 8 * HH; i += 256) {
        ((float*)sh_h)[i] = 0.0f;
        ((float*)sh_c)[i] = 0.0f;
    }
    __syncthreads();

    const int j0 = tid, j1 = tid + 256;
    for (int s = 0; s < LL; s++) {
        const int t = dir ? (LL - 1 - s) : s;
        u64 acc[4][2];
#pragma unroll
        for (int a = 0; a < 4; a++) { acc[a][0] = 0ull; acc[a][1] = 0ull; }

#pragma unroll 4
        for (int k = 0; k < HH; k++) {
            float w0 = W[k * GATES + j0];           // coalesced: j adjacent across threads
            float w1 = W[k * GATES + j1];
            u64 wa = pack2(w0, w0);
            u64 wb = pack2(w1, w1);
            ulonglong2 hA = *(const ulonglong2*)(&sh_h[k][0]);  // rows 0..3 (broadcast)
            ulonglong2 hB = *(const ulonglong2*)(&sh_h[k][4]);  // rows 4..7
            ffma2(acc[0][0], hA.x, wa); ffma2(acc[0][1], hA.x, wb);
            ffma2(acc[1][0], hA.y, wa); ffma2(acc[1][1], hA.y, wb);
            ffma2(acc[2][0], hB.x, wa); ffma2(acc[2][1], hB.x, wb);
            ffma2(acc[3][0], hB.y, wa); ffma2(acc[3][1], hB.y, wb);
        }

#pragma unroll
        for (int rp = 0; rp < 4; rp++) {
            float l0, h0, l1, h1;
            unpack2(acc[rp][0], l0, h0);
            unpack2(acc[rp][1], l1, h1);
            const int r0 = rp * 2, r1 = rp * 2 + 1;
            const size_t base0 = ((size_t)(b0 + r0) * LL + t) * 1024 + (size_t)dir * GATES;
            const size_t base1 = ((size_t)(b0 + r1) * LL + t) * 1024 + (size_t)dir * GATES;
            sh_g[r0][j0] = l0 + xg[base0 + j0];
            sh_g[r1][j0] = h0 + xg[base1 + j0];
            sh_g[r0][j1] = l1 + xg[base0 + j1];
            sh_g[r1][j1] = h1 + xg[base1 + j1];
        }
        __syncthreads();

        // cell update: gate order i,f,g,o (PyTorch)
#pragma unroll
        for (int u = 0; u < 4; u++) {
            const int cell = u * 256 + tid;
            const int r = cell >> 7, k = cell & 127;
            const float gi = sh_g[r][k];
            const float gf = sh_g[r][HH + k];
            const float gg = sh_g[r][2 * HH + k];
            const float go = sh_g[r][3 * HH + k];
            const float cn = sigm(gf) * sh_c[r][k] + sigm(gi) * tanh_acc(gg);
            sh_c[r][k] = cn;
            const float hn = sigm(go) * tanh_acc(cn);
            sh_h[k][r] = hn;
            hout[((size_t)(b0 + r) * LL + t) * DD + dir * HH + k] = hn;
        }
        __syncthreads();
    }
}

// ---------------- tag projection: logits = leaky(h2 @ Wt^T + bt), T=6 --------
__global__ void __launch_bounds__(256) tag_kernel(
    const float* __restrict__ h2, const float* __restrict__ Wt,
    const float* __restrict__ bt, float* __restrict__ logits)
{
    const int warp = threadIdx.x >> 5, lane = threadIdx.x & 31;
    const int m = blockIdx.x * 8 + warp;
    const float* row = h2 + (size_t)m * DD;
    float4 x0 = *(const float4*)(row + lane * 4);
    float4 x1 = *(const float4*)(row + 128 + lane * 4);
    float acc[TT];
#pragma unroll
    for (int t = 0; t < TT; t++) {
        const float* w = Wt + t * DD;
        float4 w0 = *(const float4*)(w + lane * 4);
        float4 w1 = *(const float4*)(w + 128 + lane * 4);
        float s = 0.0f;
        s = fmaf(x0.x, w0.x, s); s = fmaf(x0.y, w0.y, s);
        s = fmaf(x0.z, w0.z, s); s = fmaf(x0.w, w0.w, s);
        s = fmaf(x1.x, w1.x, s); s = fmaf(x1.y, w1.y, s);
        s = fmaf(x1.z, w1.z, s); s = fmaf(x1.w, w1.w, s);
        acc[t] = s;
    }
#pragma unroll
    for (int t = 0; t < TT; t++)
#pragma unroll
        for (int off = 16; off; off >>= 1)
            acc[t] += __shfl_xor_sync(0xFFFFFFFFu, acc[t], off);
    if (lane < TT) {
        float v = 0.0f;
#pragma unroll
        for (int t = 0; t < TT; t++) if (lane == t) v = acc[t];
        v = leaky(v + bt[lane]);
        logits[(size_t)m * TT + lane] = v;
    }
}

// ---------------- Viterbi decode: 1 block per sequence -----------------------
__global__ void __launch_bounds__(32) viterbi_kernel(
    const float* __restrict__ logits, const float* __restrict__ trans,
    float* __restrict__ out)
{
    const int b = blockIdx.x;
    const int j = threadIdx.x;
    __shared__ float tr[TT * TT];
    __shared__ float prev[8], cur[8];
    __shared__ unsigned char bp[LL][TT];
    if (j < TT * TT) tr[j] = trans[j];
    const float* lg = logits + (size_t)b * LL * TT;
    if (j < TT) prev[j] = lg[j];
    __syncwarp();
    for (int l = 1; l < LL; l++) {
        if (j < TT) {
            float best = prev[0] + tr[0 * TT + j];
            int arg = 0;
#pragma unroll
            for (int i = 1; i < TT; i++) {
                float v = prev[i] + tr[i * TT + j];
                if (v > best) { best = v; arg = i; }     // first-max tie-break (jnp.argmax)
            }
            cur[j] = lg[l * TT + j] + best;
            bp[l][j] = (unsigned char)arg;
        }
        __syncwarp();
        if (j < TT) prev[j] = cur[j];
        __syncwarp();
    }
    if (j == 0) {
        float best = prev[0]; int arg = 0;
#pragma unroll
        for (int i = 1; i < TT; i++)
            if (prev[i] > best) { best = prev[i]; arg = i; }
        out[b] = best;
        float* path = out + BB + (size_t)b * LL;
        int tag = arg;
        path[LL - 1] = (float)tag;
        for (int l = LL - 1; l >= 1; l--) {
            tag = bp[l][tag];
            path[l - 1] = (float)tag;
        }
    }
}

// ---------------- launch ------------------------------------------------------
extern "C" void kernel_launch(void* const* d_in, const int* in_sizes, int n_in,
                              void* d_out, int out_size)
{
    const int*   sentences = (const int*)d_in[0];
    // d_in[1] = real_length (always L, unused)
    const float* emb    = (const float*)d_in[2];
    const float* Wih_f  = (const float*)d_in[3];
    const float* Whh_f  = (const float*)d_in[4];
    const float* bih_f  = (const float*)d_in[5];
    const float* bhh_f  = (const float*)d_in[6];
    const float* Wih_b  = (const float*)d_in[7];
    const float* Whh_b  = (const float*)d_in[8];
    const float* bih_b  = (const float*)d_in[9];
    const float* bhh_b  = (const float*)d_in[10];
    const float* W1     = (const float*)d_in[11];
    const float* b1     = (const float*)d_in[12];
    const float* W2     = (const float*)d_in[13];
    const float* b2     = (const float*)d_in[14];
    const float* Wt     = (const float*)d_in[15];
    const float* bt     = (const float*)d_in[16];
    const float* trans  = (const float*)d_in[17];
    float* out = (float*)d_out;

    float *p_xg, *p_h, *p_h1, *p_h2, *p_logits, *p_Wstack, *p_bstack, *p_Wf, *p_Wb;
    cudaGetSymbolAddress((void**)&p_xg,     g_xg);
    cudaGetSymbolAddress((void**)&p_h,      g_h);
    cudaGetSymbolAddress((void**)&p_h1,     g_h1);
    cudaGetSymbolAddress((void**)&p_h2,     g_h2);
    cudaGetSymbolAddress((void**)&p_logits, g_logits);
    cudaGetSymbolAddress((void**)&p_Wstack, g_Wstack);
    cudaGetSymbolAddress((void**)&p_bstack, g_bstack);
    cudaGetSymbolAddress((void**)&p_Wf,     g_WhhT_f);
    cudaGetSymbolAddress((void**)&p_Wb,     g_WhhT_b);

    prep_kernel<<<512, 256>>>(Wih_f, Wih_b, bih_f, bhh_f, bih_b, bhh_b, Whh_f, Whh_b);

    // xg = gather(emb)[B*L, E] @ [Wih_f;Wih_b]^T + (bih+bhh)
    gemm64x64<1, 0><<<dim3(16, MROWS / 64), 256>>>(
        nullptr, sentences, emb, p_Wstack, p_bstack, p_xg, 1024, EE);

    lstm_kernel<<<128, 256>>>(p_xg, p_Wf, p_Wb, p_h);

    gemm64x64<0, 1><<<dim3(4, MROWS / 64), 256>>>(
        p_h, nullptr, nullptr, W1, b1, p_h1, DD, DD);
    gemm64x64<0, 1><<<dim3(4, MROWS / 64), 256>>>(
        p_h1, nullptr, nullptr, W2, b2, p_h2, DD, DD);

    tag_kernel<<<MROWS / 8, 256>>>(p_h2, Wt, bt, p_logits);

    viterbi_kernel<<<BB, 32>>>(p_logits, trans, out);

    (void)in_sizes; (void)n_in; (void)out_size;
}